// round 17
// baseline (speedup 1.0000x reference)
#include <cuda_runtime.h>
#include <cstdint>

// PDHG L1 solver: x = sh(x - a*A^T u, a); u += b*(A(2x_new - x_old) - b_vec)
// bs=32, m=256, n=512, iters=1000, alpha=beta=0.02
//
// 32 clusters x 4 CTAs (one per batch). Each CTA owns 64 rows of A:
// SMEM row-major copy (A*y phase) + register column copy packed as f32x2
// pairs (A^T u phase). u partitioned per CTA; only the 512-float partial
// A^T u is exchanged — PUSH-based via st.async.shared::cluster into the
// peers' interleaved receive buffers, signalled with mbarrier complete_tx
// (no barrier.cluster, no remote loads on the critical path).

#define BS      32
#define M       256
#define N       512
#define CLUSTER 4
#define MLOC    (M / CLUSTER)   // 64
#define THREADS 512
#define ITERS   1000
#define ALPHA   0.02f
#define BETA    0.02f

// SMEM float layout
#define OFF_A     0
#define OFF_RBUF  (MLOC * N)                 // 32768 : rbuf[2][N][4] interleaved by src rank
#define OFF_X     (OFF_RBUF + 2 * N * 4)     // 36864
#define OFF_Y     (OFF_X + N)
#define OFF_U     (OFF_Y + N)
#define OFF_B     (OFF_U + MLOC)
#define OFF_MBAR  (OFF_B + MLOC)             // 2 mbarriers (4 floats)
#define SMEM_FLOATS (OFF_MBAR + 4)
#define SMEM_BYTES  (SMEM_FLOATS * 4)

#define TX_BYTES  ((CLUSTER - 1) * N * 4)    // 6144 bytes expected per phase

typedef unsigned long long ull;

__device__ __forceinline__ uint32_t smem_u32(const void* p) {
    uint32_t a;
    asm("{ .reg .u64 t; cvta.to.shared.u64 t, %1; cvt.u32.u64 %0, t; }"
        : "=r"(a) : "l"(p));
    return a;
}

__device__ __forceinline__ void cluster_sync_() {
    asm volatile("barrier.cluster.arrive.aligned;" ::: "memory");
    asm volatile("barrier.cluster.wait.aligned;" ::: "memory");
}

__device__ __forceinline__ void fma2(ull& d, ull a, ull b) {
    asm("fma.rn.f32x2 %0, %1, %2, %0;" : "+l"(d) : "l"(a), "l"(b));
}
__device__ __forceinline__ ull add2(ull a, ull b) {
    ull d; asm("add.rn.f32x2 %0, %1, %2;" : "=l"(d) : "l"(a), "l"(b)); return d;
}
__device__ __forceinline__ ull pack2(float lo, float hi) {
    ull d; asm("mov.b64 %0, {%1, %2};" : "=l"(d) : "f"(lo), "f"(hi)); return d;
}
__device__ __forceinline__ float hsum2(ull v) {
    float lo, hi; asm("mov.b64 {%0, %1}, %2;" : "=f"(lo), "=f"(hi) : "l"(v));
    return lo + hi;
}

__device__ __forceinline__ void mbar_wait(uint32_t mbar, uint32_t parity) {
    asm volatile(
        "{\n\t.reg .pred P;\n\t"
        "LW_%=:\n\t"
        "mbarrier.try_wait.parity.acquire.cluster.shared::cta.b64 P, [%0], %1, 0x989680;\n\t"
        "@P bra.uni LD_%=;\n\t"
        "bra.uni LW_%=;\n\t"
        "LD_%=:\n\t}"
        :: "r"(mbar), "r"(parity) : "memory");
}

extern "C" __global__ void __launch_bounds__(THREADS, 1) __cluster_dims__(CLUSTER, 1, 1)
pdhg_kernel(const float* __restrict__ Ag, const float* __restrict__ bg,
            float* __restrict__ out)
{
    extern __shared__ float smem_f[];
    float* A_s = smem_f + OFF_A;
    float* rb  = smem_f + OFF_RBUF;     // [2][N*4] : rbuf[pb][tid*4 + src_rank]
    float* x_s = smem_f + OFF_X;
    float* y_s = smem_f + OFF_Y;
    float* u_s = smem_f + OFF_U;
    float* b_s = smem_f + OFF_B;

    const int tid  = threadIdx.x;
    const int warp = tid >> 5;
    const int lane = tid & 31;

    uint32_t rank;
    asm("mov.u32 %0, %%cluster_ctarank;" : "=r"(rank));
    const int batch = blockIdx.x / CLUSTER;

    const float* Abase = Ag + (size_t)batch * M * N + (size_t)rank * MLOC * N;

    // ---- Prologue: load A slice (64x512) into SMEM ----
    {
        const float4* Ain = (const float4*)Abase;
        float4* As4 = (float4*)A_s;
        #pragma unroll
        for (int k = 0; k < (MLOC * N / 4) / THREADS; k++)   // 16
            As4[tid + k * THREADS] = Ain[tid + k * THREADS];
    }
    if (tid < MLOC) {
        u_s[tid] = 0.0f;
        b_s[tid] = bg[batch * M + rank * MLOC + tid];
    }
    x_s[tid] = 0.0f;

    const uint32_t mbar0 = smem_u32(smem_f + OFF_MBAR);
    const uint32_t mbar1 = mbar0 + 8;
    if (tid == 0) {
        asm volatile("mbarrier.init.shared.b64 [%0], 1;" :: "r"(mbar0) : "memory");
        asm volatile("mbarrier.init.shared.b64 [%0], 1;" :: "r"(mbar1) : "memory");
    }
    __syncthreads();
    cluster_sync_();   // peers' mbarriers + smem ready before any st.async

    // ---- Register column copy, packed as f32x2 over row pairs ----
    ull aull[MLOC / 2];
    #pragma unroll
    for (int k = 0; k < MLOC / 2; k++)
        aull[k] = pack2(A_s[(2 * k) * N + tid], A_s[(2 * k + 1) * N + tid]);

    // ---- Precompute remote addresses (split regs per parity, no arrays[pb]) ----
    uint32_t st0[CLUSTER], st1[CLUSTER], mb0[CLUSTER], mb1[CLUSTER];
    {
        uint32_t l0 = smem_u32(rb + 0 * N * 4 + tid * 4 + rank);
        uint32_t l1 = smem_u32(rb + 1 * N * 4 + tid * 4 + rank);
        #pragma unroll
        for (int tr = 0; tr < CLUSTER; tr++) {
            asm("mapa.shared::cluster.u32 %0, %1, %2;" : "=r"(st0[tr]) : "r"(l0), "r"(tr));
            asm("mapa.shared::cluster.u32 %0, %1, %2;" : "=r"(st1[tr]) : "r"(l1), "r"(tr));
            asm("mapa.shared::cluster.u32 %0, %1, %2;" : "=r"(mb0[tr]) : "r"(mbar0), "r"(tr));
            asm("mapa.shared::cluster.u32 %0, %1, %2;" : "=r"(mb1[tr]) : "r"(mbar1), "r"(tr));
        }
    }

    int parA = 0, parB = 0;
    for (int it = 0; it < ITERS; it++) {
        const int pb = it & 1;
        const uint32_t mbad = pb ? mbar1 : mbar0;

        if (tid == 0)
            asm volatile("mbarrier.arrive.expect_tx.shared.b64 _, [%0], %1;"
                         :: "r"(mbad), "r"((uint32_t)TX_BYTES) : "memory");

        // ---- Phase 1: acc = sum_{i local} A[i][tid] * u[i]  (packed f32x2)
        ull acc0 = 0ull, acc1 = 0ull;
        const ulonglong2* uu2 = (const ulonglong2*)u_s;   // 16 x 128-bit
        #pragma unroll
        for (int k = 0; k < MLOC / 4; k++) {
            ulonglong2 up = uu2[k];
            fma2(acc0, aull[2 * k + 0], up.x);
            fma2(acc1, aull[2 * k + 1], up.y);
        }
        const float acc = hsum2(add2(acc0, acc1));

        // own partial -> local rbuf slot (read back by this same thread)
        rb[pb * N * 4 + tid * 4 + rank] = acc;

        // push partial to the 3 peers (fire-and-forget, tx-signalled)
        {
            const uint32_t abits = __float_as_uint(acc);
            #pragma unroll
            for (int tr = 0; tr < CLUSTER; tr++) {
                if ((uint32_t)tr != rank) {
                    uint32_t dst = pb ? st1[tr] : st0[tr];
                    uint32_t rmb = pb ? mb1[tr] : mb0[tr];
                    asm volatile(
                        "st.async.shared::cluster.mbarrier::complete_tx::bytes.b32 "
                        "[%0], %1, [%2];"
                        :: "r"(dst), "r"(abits), "r"(rmb) : "memory");
                }
            }
        }

        // ---- Wait for 3 peer partials, then sum all 4 in fixed rank order
        mbar_wait(mbad, pb ? parB : parA);
        parB ^= pb; parA ^= (pb ^ 1);

        float4 p = ((const float4*)(rb + pb * N * 4))[tid];   // one LDS.128
        float v = ((p.x + p.y) + p.z) + p.w;                  // rank order 0..3

        // ---- x update + overrelaxed y ----
        float xo = x_s[tid];
        float z  = fmaf(-ALPHA, v, xo);
        float xn = fmaxf(z - ALPHA, 0.0f) - fmaxf(-z - ALPHA, 0.0f);
        x_s[tid] = xn;
        y_s[tid] = 2.0f * xn - xo;
        __syncthreads();

        // ---- Phase 3: w[i] = A[i][:] . y for 4 local rows per warp (f32x2)
        const ulonglong2* y2 = (const ulonglong2*)y_s;
        ulonglong2 Y0 = y2[lane +  0];
        ulonglong2 Y1 = y2[lane + 32];
        ulonglong2 Y2 = y2[lane + 64];
        ulonglong2 Y3 = y2[lane + 96];

        #pragma unroll
        for (int rr = 0; rr < 4; rr++) {
            int i = warp * 4 + rr;
            const ulonglong2* Ar = (const ulonglong2*)(A_s + i * N);
            ulonglong2 a0 = Ar[lane +  0];
            ulonglong2 a1 = Ar[lane + 32];
            ulonglong2 a2 = Ar[lane + 64];
            ulonglong2 a3 = Ar[lane + 96];
            ull s0 = 0ull, s1 = 0ull;
            fma2(s0, a0.x, Y0.x); fma2(s1, a0.y, Y0.y);
            fma2(s0, a1.x, Y1.x); fma2(s1, a1.y, Y1.y);
            fma2(s0, a2.x, Y2.x); fma2(s1, a2.y, Y2.y);
            fma2(s0, a3.x, Y3.x); fma2(s1, a3.y, Y3.y);
            float s = hsum2(add2(s0, s1));
            #pragma unroll
            for (int off = 16; off > 0; off >>= 1)
                s += __shfl_xor_sync(0xFFFFFFFFu, s, off);
            if (lane == 0)
                u_s[i] = fmaf(BETA, s - b_s[i], u_s[i]);
        }
        __syncthreads();   // u_s ready for next phase 1
    }

    // no CTA may exit while peers' st.async into it could be in flight
    cluster_sync_();

    if (rank == 0)
        out[batch * N + tid] = x_s[tid];
}

extern "C" void kernel_launch(void* const* d_in, const int* in_sizes, int n_in,
                              void* d_out, int out_size)
{
    (void)in_sizes; (void)n_in; (void)out_size;
    const float* A = (const float*)d_in[0];   // (32,256,512) f32
    const float* b = (const float*)d_in[1];   // (32,256)     f32
    float* out = (float*)d_out;               // (32,512)     f32

    cudaFuncSetAttribute(pdhg_kernel,
                         cudaFuncAttributeMaxDynamicSharedMemorySize,
                         SMEM_BYTES);
    pdhg_kernel<<<BS * CLUSTER, THREADS, SMEM_BYTES>>>(A, b, out);
}